// round 6
// baseline (speedup 1.0000x reference)
#include <cuda_runtime.h>
#include <cuda_fp16.h>
#include <math.h>
#include <stdint.h>

#define B_ 1024
#define S_ 254
#define C_ 2
#define H_ 1024
#define NSTEPS 50
#define DT 0.02f

// ===================== helpers =============================================
__device__ __forceinline__ uint32_t smem_to_u32(const void* p) {
    uint32_t a;
    asm("{ .reg .u64 t; cvta.to.shared.u64 t, %1; cvt.u32.u64 %0, t; }" : "=r"(a) : "l"(p));
    return a;
}
#define CP_ASYNC16(dst, src) \
    asm volatile("cp.async.cg.shared.global [%0], [%1], 16;" :: "r"(dst), "l"(src) : "memory")
#define CP_COMMIT() asm volatile("cp.async.commit_group;" ::: "memory")
#define CP_WAIT2() asm volatile("cp.async.wait_group 2;" ::: "memory")
#define CP_WAIT0() asm volatile("cp.async.wait_group 0;" ::: "memory")

__device__ __forceinline__ void ldsm4(uint32_t* r, uint32_t addr) {
    asm volatile("ldmatrix.sync.aligned.m8n8.x4.shared.b16 {%0,%1,%2,%3}, [%4];"
        : "=r"(r[0]), "=r"(r[1]), "=r"(r[2]), "=r"(r[3]) : "r"(addr));
}
__device__ __forceinline__ void mma16816h(float* c, const uint32_t* a, const uint32_t* b) {
    asm volatile("mma.sync.aligned.m16n8k16.row.col.f32.f16.f16.f32 "
        "{%0,%1,%2,%3}, {%4,%5,%6,%7}, {%8,%9}, {%0,%1,%2,%3};"
        : "+f"(c[0]), "+f"(c[1]), "+f"(c[2]), "+f"(c[3])
        : "r"(a[0]), "r"(a[1]), "r"(a[2]), "r"(a[3]), "r"(b[0]), "r"(b[1]));
}

__device__ __forceinline__ float silu_f(float v) { return v / (1.0f + __expf(-v)); }

// acquire-spin until *p >= target (tid0 spins, block syncs)
__device__ __forceinline__ void acq_wait(const int* p, int target, int tid) {
    if (tid == 0) {
        int v;
        do {
            asm volatile("ld.global.acquire.gpu.b32 %0, [%1];" : "=r"(v) : "l"(p));
            if (v >= target) break;
            __nanosleep(32);
        } while (true);
    }
    __syncthreads();
}
// release-increment of counter after this CTA's writes
__device__ __forceinline__ void rel_post(int* p, int tid) {
    __threadfence();
    __syncthreads();
    if (tid == 0) atomicAdd(p, 1);
}

// ===================== scratch (device globals, no allocs) ==================
__device__ float g_base0[B_ * H_];
__device__ float g_tvec[NSTEPS * H_];
__device__ __half g_bufA[B_ * H_];
__device__ __half g_bufB[B_ * H_];
__device__ __half g_w16[3][H_ * H_];   // fp16 [N,K] transposed
__device__ int g_cnt[32];              // [0..7]=cnt1, [8..15]=cnt2, [16..23]=cnt3, [24..31]=fcnt

// ===================== weight transpose to fp16 =============================
__global__ void wconv_kernel(const float* __restrict__ W, __half* __restrict__ w16) {
    __shared__ float t[32][33];
    const int k0 = blockIdx.y * 32, n0 = blockIdx.x * 32;
    const int tx = threadIdx.x, ty = threadIdx.y;
    for (int i = ty; i < 32; i += 8)
        t[i][tx] = W[(size_t)(k0 + i) * H_ + n0 + tx];
    __syncthreads();
    for (int i = ty; i < 32; i += 8)
        w16[(size_t)(n0 + i) * H_ + k0 + tx] = __float2half_rn(t[tx][i]);
}

// ===================== time-embedding contribution ==========================
__global__ __launch_bounds__(128) void tvec_kernel(const float* __restrict__ W0,
                                                   float* __restrict__ tvec) {
    __shared__ float temb[64];
    const int step = blockIdx.x;
    const int tid = threadIdx.x;
    const float t = (float)step * DT;
    if (tid < 64) {
        int k = tid & 31;
        float freq = expf(-9.210340371976184f * (float)k / 31.0f);
        float ang = t * freq;
        temb[tid] = (tid < 32) ? sinf(ang) : cosf(ang);
    }
    __syncthreads();
    const int j = blockIdx.y * 128 + tid;
    float acc = 0.0f;
    #pragma unroll
    for (int k = 0; k < 64; k++)
        acc += temb[k] * W0[(size_t)(256 + k) * H_ + j];
    tvec[step * H_ + j] = acc;
}

__global__ void zero_cnt_kernel(int* c) {
    if (threadIdx.x < 32) c[threadIdx.x] = 0;
}

// ===================== fp32 SGEMM for base0 (K=254, one-time) ===============
#define BM 128
#define BN 64
#define BKK 16
__global__ __launch_bounds__(256) void sgemm_kernel(
    const float* __restrict__ A, int lda,
    const float* __restrict__ Bm, int ldb,
    const float* __restrict__ bias,
    float* __restrict__ Cm, int ldc, int K)
{
    __shared__ __align__(16) float As[2][BKK][BM + 4];
    __shared__ __align__(16) float Bs[2][BKK][BN];
    const int tid = threadIdx.x;
    const int tx = tid & 15, ty = tid >> 4;
    const int row0 = blockIdx.y * BM, col0 = blockIdx.x * BN;
    const int m0 = ty * 8, n0 = tx * 4;
    const int arow = tid >> 2, akq = (tid & 3) * 4;
    const int bk = tid >> 4, bn = (tid & 15) * 4;

    float acc[8][4];
    #pragma unroll
    for (int i = 0; i < 8; i++)
        #pragma unroll
        for (int j = 0; j < 4; j++) acc[i][j] = 0.0f;
    float4 ra[2], rb;

    auto gload = [&](int kt) {
        const int kbase = kt * BKK;
        #pragma unroll
        for (int i = 0; i < 2; i++) {
            int r = arow + i * 64, k = kbase + akq;
            const float* p = A + (size_t)(row0 + r) * lda + k;
            float4 v;
            v.x = (k + 0 < K) ? p[0] : 0.0f;
            v.y = (k + 1 < K) ? p[1] : 0.0f;
            v.z = (k + 2 < K) ? p[2] : 0.0f;
            v.w = (k + 3 < K) ? p[3] : 0.0f;
            ra[i] = v;
        }
        int k = kbase + bk;
        const float* p = Bm + (size_t)k * ldb + col0 + bn;
        rb = (k < K) ? *reinterpret_cast<const float4*>(p) : make_float4(0, 0, 0, 0);
    };
    auto sstore = [&](int buf) {
        #pragma unroll
        for (int i = 0; i < 2; i++) {
            int r = arow + i * 64;
            As[buf][akq + 0][r] = ra[i].x;
            As[buf][akq + 1][r] = ra[i].y;
            As[buf][akq + 2][r] = ra[i].z;
            As[buf][akq + 3][r] = ra[i].w;
        }
        *reinterpret_cast<float4*>(&Bs[buf][bk][bn]) = rb;
    };

    const int ktiles = (K + BKK - 1) / BKK;
    gload(0); sstore(0); __syncthreads();
    for (int kt = 0; kt < ktiles; kt++) {
        const int buf = kt & 1;
        if (kt + 1 < ktiles) gload(kt + 1);
        #pragma unroll
        for (int kk = 0; kk < BKK; kk++) {
            float a[8], bv[4];
            #pragma unroll
            for (int i = 0; i < 8; i++) a[i] = As[buf][kk][m0 + i];
            #pragma unroll
            for (int j = 0; j < 4; j++) bv[j] = Bs[buf][kk][n0 + j];
            #pragma unroll
            for (int i = 0; i < 8; i++)
                #pragma unroll
                for (int j = 0; j < 4; j++)
                    acc[i][j] = fmaf(a[i], bv[j], acc[i][j]);
        }
        if (kt + 1 < ktiles) sstore(buf ^ 1);
        __syncthreads();
    }
    float bb[4];
    #pragma unroll
    for (int j = 0; j < 4; j++) bb[j] = bias[col0 + n0 + j];
    #pragma unroll
    for (int i = 0; i < 8; i++) {
        const int m = row0 + m0 + i;
        float4 o;
        o.x = acc[i][0] + bb[0]; o.y = acc[i][1] + bb[1];
        o.z = acc[i][2] + bb[2]; o.w = acc[i][3] + bb[3];
        *reinterpret_cast<float4*>(Cm + (size_t)m * ldc + col0 + n0) = o;
    }
}

// ===================== GEMM device function (fp16 HMMA) =====================
#define GBM 128
#define GBN 64
#define GBK 32
#define GSTAGES 4
#define OFF_A 0
#define OFF_B 8192
#define STAGE_BYTES 12288
#define GSMEM_TOTAL (GSTAGES * STAGE_BYTES)

__device__ __forceinline__ uint32_t soff(int r, int ch) {
    return (uint32_t)(r * 64 + (((ch ^ (r >> 1)) & 3) << 4));
}

__device__ void gemm_dev(uint32_t sbase, const __half* __restrict__ A,
                         const __half* __restrict__ W,
                         const float* __restrict__ bias,
                         __half* __restrict__ outC,
                         int row0, int col0, int tid)
{
    auto load_stage = [&](int kt) {
        const uint32_t sb = sbase + (uint32_t)(kt % GSTAGES) * STAGE_BYTES;
        const int kb = kt * GBK;
        #pragma unroll
        for (int i = 0; i < 2; i++) {
            int c = tid + i * 256;
            int r = c >> 2, ch = c & 3;
            CP_ASYNC16(sb + OFF_A + soff(r, ch), A + (size_t)(row0 + r) * H_ + kb + ch * 8);
        }
        {
            int r = tid >> 2, ch = tid & 3;
            CP_ASYNC16(sb + OFF_B + soff(r, ch), W + (size_t)(col0 + r) * H_ + kb + ch * 8);
        }
    };

    const int lane = tid & 31;
    const int wid = tid >> 5;
    const int wm = wid & 3;
    const int wn = wid >> 2;

    float acc[2][4][4];
    #pragma unroll
    for (int mi = 0; mi < 2; mi++)
        #pragma unroll
        for (int ni = 0; ni < 4; ni++)
            #pragma unroll
            for (int q = 0; q < 4; q++) acc[mi][ni][q] = 0.0f;

    const int a_r = wm * 32 + (lane & 15);
    const int a_half = lane >> 4;
    const int b_r = wn * 32 + (lane & 7) + ((lane >> 4) << 3);
    const int b_half = (lane >> 3) & 1;

    load_stage(0); CP_COMMIT();
    load_stage(1); CP_COMMIT();
    load_stage(2); CP_COMMIT();

    const int NKT = H_ / GBK;  // 32
    for (int kt = 0; kt < NKT; kt++) {
        CP_WAIT2();
        __syncthreads();

        const uint32_t sb = sbase + (uint32_t)(kt % GSTAGES) * STAGE_BYTES;

        uint32_t af[2][2][4];
        uint32_t bf[2][2][4];
        #pragma unroll
        for (int ks = 0; ks < 2; ks++) {
            #pragma unroll
            for (int mi = 0; mi < 2; mi++)
                ldsm4(af[ks][mi], sb + OFF_A + soff(a_r + mi * 16, ks * 2 + a_half));
            #pragma unroll
            for (int nt = 0; nt < 2; nt++)
                ldsm4(bf[ks][nt], sb + OFF_B + soff(b_r + nt * 16, ks * 2 + b_half));
        }

        if (kt + 3 < NKT) load_stage(kt + 3);
        CP_COMMIT();

        #pragma unroll
        for (int ks = 0; ks < 2; ks++)
            #pragma unroll
            for (int mi = 0; mi < 2; mi++)
                #pragma unroll
                for (int ni = 0; ni < 4; ni++)
                    mma16816h(acc[mi][ni], af[ks][mi], &bf[ks][ni >> 1][(ni & 1) * 2]);
    }

    // epilogue: bias + silu, packed half2 stores
    #pragma unroll
    for (int mi = 0; mi < 2; mi++) {
        const int r0g = row0 + wm * 32 + mi * 16 + (lane >> 2);
        #pragma unroll
        for (int ni = 0; ni < 4; ni++) {
            const int cg = col0 + wn * 32 + ni * 8 + (lane & 3) * 2;
            float2 bb = *reinterpret_cast<const float2*>(bias + cg);
            __half2 p0 = __floats2half2_rn(silu_f(acc[mi][ni][0] + bb.x),
                                           silu_f(acc[mi][ni][1] + bb.y));
            __half2 p1 = __floats2half2_rn(silu_f(acc[mi][ni][2] + bb.x),
                                           silu_f(acc[mi][ni][3] + bb.y));
            *reinterpret_cast<__half2*>(outC + (size_t)r0g * H_ + cg) = p0;
            *reinterpret_cast<__half2*>(outC + (size_t)(r0g + 8) * H_ + cg) = p1;
        }
    }

    // drain async pipe before smem reuse by next phase
    CP_WAIT0();
    __syncthreads();
}

// ===================== persistent mega kernel ===============================
// grid (16, 8): bx = n-block (64 cols), by = m-block (128 rows).
// Owns fuse for rows [by*128 + bx*8, +8).
__global__ __launch_bounds__(256, 1) void mega_kernel(
    const float* __restrict__ base0, const float* __restrict__ tvec,
    const float* __restrict__ w254, const float* __restrict__ w255,
    const __half* __restrict__ w16,
    const float* __restrict__ b1, const float* __restrict__ b2,
    const float* __restrict__ b3,
    const float* __restrict__ W4, const float* __restrict__ b4,
    const float* __restrict__ x0,
    __half* __restrict__ bufA, __half* __restrict__ bufB,
    int* __restrict__ cnt, float* __restrict__ out)
{
    extern __shared__ __align__(1024) char gs[];
    const uint32_t sbase = smem_to_u32(gs);
    const int tid = threadIdx.x;
    const int bx = blockIdx.x, by = blockIdx.y;
    const int row0 = by * GBM;
    const int col0 = bx * GBN;
    const int rbase = by * 128 + bx * 8;   // 8 fuse-owned rows

    int* cnt1 = cnt;
    int* cnt2 = cnt + 8;
    int* cnt3 = cnt + 16;
    int* fcnt = cnt + 24;

    __shared__ float sx[8][2];
    if (tid < 8) {
        sx[tid][0] = x0[2 * (rbase + tid)];
        sx[tid][1] = x0[2 * (rbase + tid) + 1];
    }
    __syncthreads();

    const int lane = tid & 31;
    const int wid = tid >> 5;

    for (int s = 0; s < NSTEPS; s++) {
        // ---------- FUSE phase: (GEMV+Euler for s>0) + layer0 -> bufA ------
        if (s > 0) {
            acq_wait(&cnt3[by], 16 * s, tid);
            // warp per row: dot(h3[row,:], W4)
            const int row = rbase + wid;
            const __half2* ph = reinterpret_cast<const __half2*>(bufB + (size_t)row * H_);
            const float4* w4q = reinterpret_cast<const float4*>(W4);
            float s0 = 0.0f, s1 = 0.0f;
            for (int j = lane; j < 512; j += 32) {
                __half2 h2 = ph[j];
                float a = __low2float(h2), b = __high2float(h2);
                float4 wq = w4q[j];   // cols 2j, 2j+1 weight pairs
                s0 += a * wq.x + b * wq.z;
                s1 += a * wq.y + b * wq.w;
            }
            #pragma unroll
            for (int o = 16; o > 0; o >>= 1) {
                s0 += __shfl_down_sync(0xffffffffu, s0, o);
                s1 += __shfl_down_sync(0xffffffffu, s1, o);
            }
            if (lane == 0) {
                sx[wid][0] += DT * (s0 + b4[0]);
                sx[wid][1] += DT * (s1 + b4[1]);
            }
            __syncthreads();
        }
        {
            const float* tv = tvec + (size_t)s * H_;
            for (int idx = tid; idx < 8 * H_; idx += 256) {
                const int r = idx >> 10;
                const int j = idx & 1023;
                const int b = rbase + r;
                float v = base0[(size_t)b * H_ + j] + tv[j]
                          + sx[r][0] * w254[j] + sx[r][1] * w255[j];
                bufA[(size_t)b * H_ + j] = __float2half_rn(silu_f(v));
            }
        }
        rel_post(&fcnt[by], tid);

        // ---------- GEMM1: bufA -> bufB ----------
        acq_wait(&fcnt[by], 16 * (s + 1), tid);
        gemm_dev(sbase, bufA, w16 + 0 * (size_t)H_ * H_, b1, bufB, row0, col0, tid);
        rel_post(&cnt1[by], tid);

        // ---------- GEMM2: bufB -> bufA ----------
        acq_wait(&cnt1[by], 16 * (s + 1), tid);
        gemm_dev(sbase, bufB, w16 + 1 * (size_t)H_ * H_, b2, bufA, row0, col0, tid);
        rel_post(&cnt2[by], tid);

        // ---------- GEMM3: bufA -> bufB ----------
        acq_wait(&cnt2[by], 16 * (s + 1), tid);
        gemm_dev(sbase, bufA, w16 + 2 * (size_t)H_ * H_, b3, bufB, row0, col0, tid);
        rel_post(&cnt3[by], tid);
    }

    // ---------- final GEMV + Euler, write out ----------
    acq_wait(&cnt3[by], 16 * NSTEPS, tid);
    {
        const int row = rbase + wid;
        const __half2* ph = reinterpret_cast<const __half2*>(bufB + (size_t)row * H_);
        const float4* w4q = reinterpret_cast<const float4*>(W4);
        float s0 = 0.0f, s1 = 0.0f;
        for (int j = lane; j < 512; j += 32) {
            __half2 h2 = ph[j];
            float a = __low2float(h2), b = __high2float(h2);
            float4 wq = w4q[j];
            s0 += a * wq.x + b * wq.z;
            s1 += a * wq.y + b * wq.w;
        }
        #pragma unroll
        for (int o = 16; o > 0; o >>= 1) {
            s0 += __shfl_down_sync(0xffffffffu, s0, o);
            s1 += __shfl_down_sync(0xffffffffu, s1, o);
        }
        if (lane == 0) {
            out[2 * row]     = sx[wid][0] + DT * (s0 + b4[0]);
            out[2 * row + 1] = sx[wid][1] + DT * (s1 + b4[1]);
        }
    }
}

// ===================== host side ============================================
extern "C" void kernel_launch(void* const* d_in, const int* in_sizes, int n_in,
                              void* d_out, int out_size)
{
    const float* state = (const float*)d_in[0];
    const float* x0    = (const float*)d_in[1];
    const float* W0    = (const float*)d_in[2];
    const float* b0    = (const float*)d_in[3];
    const float* W1    = (const float*)d_in[4];
    const float* b1    = (const float*)d_in[5];
    const float* W2    = (const float*)d_in[6];
    const float* b2    = (const float*)d_in[7];
    const float* W3    = (const float*)d_in[8];
    const float* b3    = (const float*)d_in[9];
    const float* W4    = (const float*)d_in[10];
    const float* b4    = (const float*)d_in[11];
    float* out = (float*)d_out;

    float *base0p, *tvecp;
    __half *bufA, *bufB, *w16;
    int* cntp;
    cudaGetSymbolAddress((void**)&base0p, g_base0);
    cudaGetSymbolAddress((void**)&tvecp,  g_tvec);
    cudaGetSymbolAddress((void**)&bufA,   g_bufA);
    cudaGetSymbolAddress((void**)&bufB,   g_bufB);
    cudaGetSymbolAddress((void**)&w16,    g_w16);
    cudaGetSymbolAddress((void**)&cntp,   g_cnt);

    static bool attr_set = false;
    if (!attr_set) {
        cudaFuncSetAttribute(mega_kernel, cudaFuncAttributeMaxDynamicSharedMemorySize,
                             GSMEM_TOTAL);
        attr_set = true;
    }

    // one-time prep
    dim3 tb(32, 8), tg(32, 32);
    wconv_kernel<<<tg, tb>>>(W1, w16 + 0 * (size_t)H_ * H_);
    wconv_kernel<<<tg, tb>>>(W2, w16 + 1 * (size_t)H_ * H_);
    wconv_kernel<<<tg, tb>>>(W3, w16 + 2 * (size_t)H_ * H_);
    tvec_kernel<<<dim3(NSTEPS, 8), 128>>>(W0, tvecp);
    sgemm_kernel<<<dim3(H_ / BN, B_ / BM), 256>>>(state, S_, W0, H_, b0, base0p, H_, S_);
    zero_cnt_kernel<<<1, 32>>>(cntp);

    const float* w254 = W0 + (size_t)254 * H_;
    const float* w255 = W0 + (size_t)255 * H_;

    dim3 ggrid(H_ / GBN, B_ / GBM);  // (16, 8) = 128 CTAs, all co-resident
    mega_kernel<<<ggrid, 256, GSMEM_TOTAL>>>(base0p, tvecp, w254, w255, w16,
                                             b1, b2, b3, W4, b4, x0,
                                             bufA, bufB, cntp, out);
}

// round 7
// speedup vs baseline: 1.1740x; 1.1740x over previous
#include <cuda_runtime.h>
#include <cuda_fp16.h>
#include <math.h>
#include <stdint.h>

#define B_ 1024
#define S_ 254
#define C_ 2
#define H_ 1024
#define NSTEPS 50
#define DT 0.02f

// ===================== helpers =============================================
__device__ __forceinline__ uint32_t smem_to_u32(const void* p) {
    uint32_t a;
    asm("{ .reg .u64 t; cvta.to.shared.u64 t, %1; cvt.u32.u64 %0, t; }" : "=r"(a) : "l"(p));
    return a;
}
#define CP_ASYNC16(dst, src) \
    asm volatile("cp.async.cg.shared.global [%0], [%1], 16;" :: "r"(dst), "l"(src) : "memory")
#define CP_COMMIT() asm volatile("cp.async.commit_group;" ::: "memory")
#define CP_WAIT1() asm volatile("cp.async.wait_group 1;" ::: "memory")

__device__ __forceinline__ void ldsm4(uint32_t* r, uint32_t addr) {
    asm volatile("ldmatrix.sync.aligned.m8n8.x4.shared.b16 {%0,%1,%2,%3}, [%4];"
        : "=r"(r[0]), "=r"(r[1]), "=r"(r[2]), "=r"(r[3]) : "r"(addr));
}
__device__ __forceinline__ void mma16816h(float* c, const uint32_t* a, const uint32_t* b) {
    asm volatile("mma.sync.aligned.m16n8k16.row.col.f32.f16.f16.f32 "
        "{%0,%1,%2,%3}, {%4,%5,%6,%7}, {%8,%9}, {%0,%1,%2,%3};"
        : "+f"(c[0]), "+f"(c[1]), "+f"(c[2]), "+f"(c[3])
        : "r"(a[0]), "r"(a[1]), "r"(a[2]), "r"(a[3]), "r"(b[0]), "r"(b[1]));
}

__device__ __forceinline__ float silu_f(float v) { return v / (1.0f + __expf(-v)); }

// ===================== scratch (device globals, no allocs) ==================
__device__ float g_base0[B_ * H_];
__device__ float g_tvec[NSTEPS * H_];
__device__ float g_x[B_ * C_];
__device__ __half g_actA[B_ * H_];
__device__ __half g_actB[B_ * H_];
__device__ __half g_w16[3][H_ * H_];   // fp16 [N,K] transposed

// ===================== weight transpose to fp16 =============================
__global__ void wconv_kernel(const float* __restrict__ W, __half* __restrict__ w16) {
    __shared__ float t[32][33];
    const int k0 = blockIdx.y * 32, n0 = blockIdx.x * 32;
    const int tx = threadIdx.x, ty = threadIdx.y;
    for (int i = ty; i < 32; i += 8)
        t[i][tx] = W[(size_t)(k0 + i) * H_ + n0 + tx];
    __syncthreads();
    for (int i = ty; i < 32; i += 8)
        w16[(size_t)(n0 + i) * H_ + k0 + tx] = __float2half_rn(t[tx][i]);
}

// ===================== time-embedding contribution ==========================
__global__ __launch_bounds__(128) void tvec_kernel(const float* __restrict__ W0,
                                                   float* __restrict__ tvec) {
    __shared__ float temb[64];
    const int step = blockIdx.x;
    const int tid = threadIdx.x;
    const float t = (float)step * DT;
    if (tid < 64) {
        int k = tid & 31;
        float freq = expf(-9.210340371976184f * (float)k / 31.0f);
        float ang = t * freq;
        temb[tid] = (tid < 32) ? sinf(ang) : cosf(ang);
    }
    __syncthreads();
    const int j = blockIdx.y * 128 + tid;
    float acc = 0.0f;
    #pragma unroll
    for (int k = 0; k < 64; k++)
        acc += temb[k] * W0[(size_t)(256 + k) * H_ + j];
    tvec[step * H_ + j] = acc;
}

// ===================== fp32 SGEMM for base0 (K=254, one-time) ===============
#define BM 128
#define BN 64
#define BKK 16
__global__ __launch_bounds__(256) void sgemm_kernel(
    const float* __restrict__ A, int lda,
    const float* __restrict__ Bm, int ldb,
    const float* __restrict__ bias,
    float* __restrict__ Cm, int ldc, int K)
{
    __shared__ __align__(16) float As[2][BKK][BM + 4];
    __shared__ __align__(16) float Bs[2][BKK][BN];
    const int tid = threadIdx.x;
    const int tx = tid & 15, ty = tid >> 4;
    const int row0 = blockIdx.y * BM, col0 = blockIdx.x * BN;
    const int m0 = ty * 8, n0 = tx * 4;
    const int arow = tid >> 2, akq = (tid & 3) * 4;
    const int bk = tid >> 4, bn = (tid & 15) * 4;

    float acc[8][4];
    #pragma unroll
    for (int i = 0; i < 8; i++)
        #pragma unroll
        for (int j = 0; j < 4; j++) acc[i][j] = 0.0f;
    float4 ra[2], rb;

    auto gload = [&](int kt) {
        const int kbase = kt * BKK;
        #pragma unroll
        for (int i = 0; i < 2; i++) {
            int r = arow + i * 64, k = kbase + akq;
            const float* p = A + (size_t)(row0 + r) * lda + k;
            float4 v;
            v.x = (k + 0 < K) ? p[0] : 0.0f;
            v.y = (k + 1 < K) ? p[1] : 0.0f;
            v.z = (k + 2 < K) ? p[2] : 0.0f;
            v.w = (k + 3 < K) ? p[3] : 0.0f;
            ra[i] = v;
        }
        int k = kbase + bk;
        const float* p = Bm + (size_t)k * ldb + col0 + bn;
        rb = (k < K) ? *reinterpret_cast<const float4*>(p) : make_float4(0, 0, 0, 0);
    };
    auto sstore = [&](int buf) {
        #pragma unroll
        for (int i = 0; i < 2; i++) {
            int r = arow + i * 64;
            As[buf][akq + 0][r] = ra[i].x;
            As[buf][akq + 1][r] = ra[i].y;
            As[buf][akq + 2][r] = ra[i].z;
            As[buf][akq + 3][r] = ra[i].w;
        }
        *reinterpret_cast<float4*>(&Bs[buf][bk][bn]) = rb;
    };

    const int ktiles = (K + BKK - 1) / BKK;
    gload(0); sstore(0); __syncthreads();
    for (int kt = 0; kt < ktiles; kt++) {
        const int buf = kt & 1;
        if (kt + 1 < ktiles) gload(kt + 1);
        #pragma unroll
        for (int kk = 0; kk < BKK; kk++) {
            float a[8], bv[4];
            #pragma unroll
            for (int i = 0; i < 8; i++) a[i] = As[buf][kk][m0 + i];
            #pragma unroll
            for (int j = 0; j < 4; j++) bv[j] = Bs[buf][kk][n0 + j];
            #pragma unroll
            for (int i = 0; i < 8; i++)
                #pragma unroll
                for (int j = 0; j < 4; j++)
                    acc[i][j] = fmaf(a[i], bv[j], acc[i][j]);
        }
        if (kt + 1 < ktiles) sstore(buf ^ 1);
        __syncthreads();
    }
    float bb[4];
    #pragma unroll
    for (int j = 0; j < 4; j++) bb[j] = bias[col0 + n0 + j];
    #pragma unroll
    for (int i = 0; i < 8; i++) {
        const int m = row0 + m0 + i;
        float4 o;
        o.x = acc[i][0] + bb[0]; o.y = acc[i][1] + bb[1];
        o.z = acc[i][2] + bb[2]; o.w = acc[i][3] + bb[3];
        *reinterpret_cast<float4*>(Cm + (size_t)m * ldc + col0 + n0) = o;
    }
}

// ===================== single-pass fp16 HMMA GEMM (BK=64, pipelined) ========
#define GBM 128
#define GBN 64
#define GBK 64
#define GSTAGES 3
#define OFF_A 0
#define OFF_B 16384
#define STAGE_BYTES 24576
#define GSMEM_TOTAL (GSTAGES * STAGE_BYTES)

// 128B rows, 8 chunks of 16B, xor-swizzled
__device__ __forceinline__ uint32_t soff(int r, int ch) {
    return (uint32_t)(r * 128 + (((ch ^ r) & 7) << 4));
}

__global__ __launch_bounds__(256, 1) void gemm_hmma(
    const __half* __restrict__ A, const __half* __restrict__ W,
    const float* __restrict__ bias, __half* __restrict__ outC)
{
    extern __shared__ __align__(1024) char gs[];
    const uint32_t sbase = smem_to_u32(gs);
    const int tid = threadIdx.x;
    const int row0 = blockIdx.y * GBM;
    const int col0 = blockIdx.x * GBN;

    auto load_stage = [&](int kt) {
        const uint32_t sb = sbase + (uint32_t)(kt % GSTAGES) * STAGE_BYTES;
        const int kb = kt * GBK;
        #pragma unroll
        for (int i = 0; i < 4; i++) {   // A: 128 rows x 8 chunks = 1024
            int c = tid + i * 256;
            int r = c >> 3, ch = c & 7;
            CP_ASYNC16(sb + OFF_A + soff(r, ch), A + (size_t)(row0 + r) * H_ + kb + ch * 8);
        }
        #pragma unroll
        for (int i = 0; i < 2; i++) {   // B: 64 rows x 8 chunks = 512
            int c = tid + i * 256;
            int r = c >> 3, ch = c & 7;
            CP_ASYNC16(sb + OFF_B + soff(r, ch), W + (size_t)(col0 + r) * H_ + kb + ch * 8);
        }
    };

    const int lane = tid & 31;
    const int wid = tid >> 5;
    const int wm = wid & 3;   // M warp
    const int wn = wid >> 2;  // N warp

    float acc[2][4][4];
    #pragma unroll
    for (int mi = 0; mi < 2; mi++)
        #pragma unroll
        for (int ni = 0; ni < 4; ni++)
            #pragma unroll
            for (int q = 0; q < 4; q++) acc[mi][ni][q] = 0.0f;

    const int a_r = wm * 32 + (lane & 15);
    const int a_half = lane >> 4;
    const int b_r = wn * 32 + (lane & 7) + ((lane >> 4) << 3);
    const int b_half = (lane >> 3) & 1;

    load_stage(0); CP_COMMIT();
    load_stage(1); CP_COMMIT();

    uint32_t af[2][2][4];   // [pp][mi][4]
    uint32_t bf[2][2][4];   // [pp][nt][4]

    const int NKT = H_ / GBK;  // 16
    for (int kt = 0; kt < NKT; kt++) {
        CP_WAIT1();
        __syncthreads();
        const uint32_t sb = sbase + (uint32_t)(kt % GSTAGES) * STAGE_BYTES;

        // fragments for ks=0
        #pragma unroll
        for (int mi = 0; mi < 2; mi++)
            ldsm4(af[0][mi], sb + OFF_A + soff(a_r + mi * 16, a_half));
        #pragma unroll
        for (int nt = 0; nt < 2; nt++)
            ldsm4(bf[0][nt], sb + OFF_B + soff(b_r + nt * 16, b_half));

        #pragma unroll
        for (int ks = 0; ks < 4; ks++) {
            const int cur = ks & 1, nxt = cur ^ 1;
            if (ks < 3) {
                const int ch = (ks + 1) * 2;
                #pragma unroll
                for (int mi = 0; mi < 2; mi++)
                    ldsm4(af[nxt][mi], sb + OFF_A + soff(a_r + mi * 16, ch + a_half));
                #pragma unroll
                for (int nt = 0; nt < 2; nt++)
                    ldsm4(bf[nxt][nt], sb + OFF_B + soff(b_r + nt * 16, ch + b_half));
            }
            if (ks == 0) {  // overlap next stage's gmem loads with MMA work
                if (kt + 2 < NKT) load_stage(kt + 2);
                CP_COMMIT();
            }
            #pragma unroll
            for (int mi = 0; mi < 2; mi++)
                #pragma unroll
                for (int ni = 0; ni < 4; ni++)
                    mma16816h(acc[mi][ni], af[cur][mi], &bf[cur][ni >> 1][(ni & 1) * 2]);
        }
    }

    // epilogue: bias + silu, packed half2 stores
    #pragma unroll
    for (int mi = 0; mi < 2; mi++) {
        const int r0g = row0 + wm * 32 + mi * 16 + (lane >> 2);
        #pragma unroll
        for (int ni = 0; ni < 4; ni++) {
            const int cg = col0 + wn * 32 + ni * 8 + (lane & 3) * 2;
            float2 bb = *reinterpret_cast<const float2*>(bias + cg);
            __half2 p0 = __floats2half2_rn(silu_f(acc[mi][ni][0] + bb.x),
                                           silu_f(acc[mi][ni][1] + bb.y));
            __half2 p1 = __floats2half2_rn(silu_f(acc[mi][ni][2] + bb.x),
                                           silu_f(acc[mi][ni][3] + bb.y));
            *reinterpret_cast<__half2*>(outC + (size_t)r0g * H_ + cg) = p0;
            *reinterpret_cast<__half2*>(outC + (size_t)(r0g + 8) * H_ + cg) = p1;
        }
    }
}

// ===================== layer-0 fused activation (step 0 only) ===============
__global__ __launch_bounds__(256) void layer0_act(
    const float* __restrict__ base0, const float* __restrict__ tvec_step,
    const float* __restrict__ w254, const float* __restrict__ w255,
    const float* __restrict__ x, __half* __restrict__ h)
{
    const int idx = blockIdx.x * blockDim.x + threadIdx.x;
    const int b = idx >> 10;
    const int j = idx & 1023;
    float v = base0[idx] + tvec_step[j] + x[2 * b] * w254[j] + x[2 * b + 1] * w255[j];
    h[idx] = __float2half_rn(silu_f(v));
}

// ===================== fused: out head + Euler + next-step layer0 ===========
// 128 blocks x 256 threads; block handles 8 rows (warp-per-row GEMV).
__global__ __launch_bounds__(256) void step_fuse(
    const __half* __restrict__ hIn,
    const float* __restrict__ W4, const float* __restrict__ b4,
    float* __restrict__ x,
    const float* __restrict__ base0, const float* __restrict__ tvec_next,
    const float* __restrict__ w254, const float* __restrict__ w255,
    __half* __restrict__ hOut)
{
    const int tid = threadIdx.x;
    const int lane = tid & 31;
    const int wid = tid >> 5;
    const int rbase = blockIdx.x * 8;

    __shared__ float sx[8][2];

    // warp-per-row GEMV: dot(h[row,:], W4[:,0:2])
    {
        const int row = rbase + wid;
        const __half2* ph = reinterpret_cast<const __half2*>(hIn + (size_t)row * H_);
        const float4* w4q = reinterpret_cast<const float4*>(W4);
        float s0 = 0.0f, s1 = 0.0f;
        #pragma unroll 4
        for (int j = lane; j < 512; j += 32) {
            __half2 h2 = ph[j];
            float a = __low2float(h2), b = __high2float(h2);
            float4 wq = w4q[j];
            s0 += a * wq.x + b * wq.z;
            s1 += a * wq.y + b * wq.w;
        }
        #pragma unroll
        for (int o = 16; o > 0; o >>= 1) {
            s0 += __shfl_down_sync(0xffffffffu, s0, o);
            s1 += __shfl_down_sync(0xffffffffu, s1, o);
        }
        if (lane == 0) {
            float xv0 = x[2 * row]     + DT * (s0 + b4[0]);
            float xv1 = x[2 * row + 1] + DT * (s1 + b4[1]);
            x[2 * row] = xv0; x[2 * row + 1] = xv1;
            sx[wid][0] = xv0; sx[wid][1] = xv1;
        }
    }
    __syncthreads();

    // layer0 for the 8 rows
    for (int idx = tid; idx < 8 * H_; idx += 256) {
        const int r = idx >> 10;
        const int j = idx & 1023;
        const int b = rbase + r;
        float v = base0[(size_t)b * H_ + j] + tvec_next[j]
                  + sx[r][0] * w254[j] + sx[r][1] * w255[j];
        hOut[(size_t)b * H_ + j] = __float2half_rn(silu_f(v));
    }
}

// ===================== final out head + Euler ===============================
__global__ __launch_bounds__(256) void out_euler(
    const __half* __restrict__ hIn,
    const float* __restrict__ W4, const float* __restrict__ b4,
    const float* __restrict__ x, float* __restrict__ out)
{
    const int tid = threadIdx.x;
    const int lane = tid & 31;
    const int wid = tid >> 5;
    const int row = blockIdx.x * 8 + wid;
    const __half2* ph = reinterpret_cast<const __half2*>(hIn + (size_t)row * H_);
    const float4* w4q = reinterpret_cast<const float4*>(W4);
    float s0 = 0.0f, s1 = 0.0f;
    #pragma unroll 4
    for (int j = lane; j < 512; j += 32) {
        __half2 h2 = ph[j];
        float a = __low2float(h2), b = __high2float(h2);
        float4 wq = w4q[j];
        s0 += a * wq.x + b * wq.z;
        s1 += a * wq.y + b * wq.w;
    }
    #pragma unroll
    for (int o = 16; o > 0; o >>= 1) {
        s0 += __shfl_down_sync(0xffffffffu, s0, o);
        s1 += __shfl_down_sync(0xffffffffu, s1, o);
    }
    if (lane == 0) {
        out[2 * row]     = x[2 * row]     + DT * (s0 + b4[0]);
        out[2 * row + 1] = x[2 * row + 1] + DT * (s1 + b4[1]);
    }
}

// ===================== host side ============================================
extern "C" void kernel_launch(void* const* d_in, const int* in_sizes, int n_in,
                              void* d_out, int out_size)
{
    const float* state = (const float*)d_in[0];
    const float* x0    = (const float*)d_in[1];
    const float* W0    = (const float*)d_in[2];
    const float* b0    = (const float*)d_in[3];
    const float* W1    = (const float*)d_in[4];
    const float* b1    = (const float*)d_in[5];
    const float* W2    = (const float*)d_in[6];
    const float* b2    = (const float*)d_in[7];
    const float* W3    = (const float*)d_in[8];
    const float* b3    = (const float*)d_in[9];
    const float* W4    = (const float*)d_in[10];
    const float* b4    = (const float*)d_in[11];
    float* out = (float*)d_out;

    float *base0p, *tvecp, *xp;
    __half *actA, *actB, *w16;
    cudaGetSymbolAddress((void**)&base0p, g_base0);
    cudaGetSymbolAddress((void**)&tvecp,  g_tvec);
    cudaGetSymbolAddress((void**)&xp,     g_x);
    cudaGetSymbolAddress((void**)&actA,   g_actA);
    cudaGetSymbolAddress((void**)&actB,   g_actB);
    cudaGetSymbolAddress((void**)&w16,    g_w16);

    static bool attr_set = false;
    if (!attr_set) {
        cudaFuncSetAttribute(gemm_hmma, cudaFuncAttributeMaxDynamicSharedMemorySize,
                             GSMEM_TOTAL);
        attr_set = true;
    }

    // one-time prep
    cudaMemcpyAsync(xp, x0, B_ * C_ * sizeof(float), cudaMemcpyDeviceToDevice);
    dim3 tb(32, 8), tg(32, 32);
    wconv_kernel<<<tg, tb>>>(W1, w16 + 0 * (size_t)H_ * H_);
    wconv_kernel<<<tg, tb>>>(W2, w16 + 1 * (size_t)H_ * H_);
    wconv_kernel<<<tg, tb>>>(W3, w16 + 2 * (size_t)H_ * H_);
    tvec_kernel<<<dim3(NSTEPS, 8), 128>>>(W0, tvecp);
    sgemm_kernel<<<dim3(H_ / BN, B_ / BM), 256>>>(state, S_, W0, H_, b0, base0p, H_, S_);

    const float* w254 = W0 + (size_t)254 * H_;
    const float* w255 = W0 + (size_t)255 * H_;

    dim3 ggrid(H_ / GBN, B_ / GBM);  // (16, 8) = 128 CTAs
    layer0_act<<<(B_ * H_) / 256, 256>>>(base0p, tvecp, w254, w255, xp, actA);
    for (int i = 0; i < NSTEPS; i++) {
        gemm_hmma<<<ggrid, 256, GSMEM_TOTAL>>>(actA, w16 + 0 * (size_t)H_ * H_, b1, actB);
        gemm_hmma<<<ggrid, 256, GSMEM_TOTAL>>>(actB, w16 + 1 * (size_t)H_ * H_, b2, actA);
        gemm_hmma<<<ggrid, 256, GSMEM_TOTAL>>>(actA, w16 + 2 * (size_t)H_ * H_, b3, actB);
        if (i + 1 < NSTEPS) {
            step_fuse<<<B_ / 8, 256>>>(actB, W4, b4, xp, base0p,
                                       tvecp + (i + 1) * H_, w254, w255, actA);
        } else {
            out_euler<<<B_ / 8, 256>>>(actB, W4, b4, xp, out);
        }
    }
}

// round 8
// speedup vs baseline: 1.1830x; 1.0077x over previous
#include <cuda_runtime.h>
#include <cuda_fp16.h>
#include <math.h>
#include <stdint.h>

#define B_ 1024
#define S_ 254
#define C_ 2
#define H_ 1024
#define NSTEPS 50
#define DT 0.02f

// ===================== helpers =============================================
__device__ __forceinline__ uint32_t smem_to_u32(const void* p) {
    uint32_t a;
    asm("{ .reg .u64 t; cvta.to.shared.u64 t, %1; cvt.u32.u64 %0, t; }" : "=r"(a) : "l"(p));
    return a;
}
#define CP_ASYNC16(dst, src) \
    asm volatile("cp.async.cg.shared.global [%0], [%1], 16;" :: "r"(dst), "l"(src) : "memory")
#define CP_COMMIT() asm volatile("cp.async.commit_group;" ::: "memory")
#define CP_WAIT1() asm volatile("cp.async.wait_group 1;" ::: "memory")

__device__ __forceinline__ void ldsm4(uint32_t* r, uint32_t addr) {
    asm volatile("ldmatrix.sync.aligned.m8n8.x4.shared.b16 {%0,%1,%2,%3}, [%4];"
        : "=r"(r[0]), "=r"(r[1]), "=r"(r[2]), "=r"(r[3]) : "r"(addr));
}
__device__ __forceinline__ void mma16816h(float* c, const uint32_t* a, const uint32_t* b) {
    asm volatile("mma.sync.aligned.m16n8k16.row.col.f32.f16.f16.f32 "
        "{%0,%1,%2,%3}, {%4,%5,%6,%7}, {%8,%9}, {%0,%1,%2,%3};"
        : "+f"(c[0]), "+f"(c[1]), "+f"(c[2]), "+f"(c[3])
        : "r"(a[0]), "r"(a[1]), "r"(a[2]), "r"(a[3]), "r"(b[0]), "r"(b[1]));
}

__device__ __forceinline__ float silu_f(float v) { return v / (1.0f + __expf(-v)); }

// ===================== scratch (device globals, no allocs) ==================
__device__ __half g_base0h[B_ * H_];
__device__ float g_tvec[NSTEPS * H_];
__device__ float g_x[B_ * C_];
__device__ __half g_actA[B_ * H_];
__device__ __half g_actB[B_ * H_];
__device__ __half g_w16[3][H_ * H_];      // fp16 [N,K] transposed
__device__ float g_part[8 * 16 * 128 * 2];  // [mblock][nblock][row][c]

// ===================== weight transpose to fp16 =============================
__global__ void wconv_kernel(const float* __restrict__ W, __half* __restrict__ w16) {
    __shared__ float t[32][33];
    const int k0 = blockIdx.y * 32, n0 = blockIdx.x * 32;
    const int tx = threadIdx.x, ty = threadIdx.y;
    for (int i = ty; i < 32; i += 8)
        t[i][tx] = W[(size_t)(k0 + i) * H_ + n0 + tx];
    __syncthreads();
    for (int i = ty; i < 32; i += 8)
        w16[(size_t)(n0 + i) * H_ + k0 + tx] = __float2half_rn(t[tx][i]);
}

// ===================== time-embedding contribution ==========================
__global__ __launch_bounds__(128) void tvec_kernel(const float* __restrict__ W0,
                                                   float* __restrict__ tvec) {
    __shared__ float temb[64];
    const int step = blockIdx.x;
    const int tid = threadIdx.x;
    const float t = (float)step * DT;
    if (tid < 64) {
        int k = tid & 31;
        float freq = expf(-9.210340371976184f * (float)k / 31.0f);
        float ang = t * freq;
        temb[tid] = (tid < 32) ? sinf(ang) : cosf(ang);
    }
    __syncthreads();
    const int j = blockIdx.y * 128 + tid;
    float acc = 0.0f;
    #pragma unroll
    for (int k = 0; k < 64; k++)
        acc += temb[k] * W0[(size_t)(256 + k) * H_ + j];
    tvec[step * H_ + j] = acc;
}

// ===================== fp32 SGEMM for base0 (K=254, one-time, fp16 out) =====
#define BM 128
#define BN 64
#define BKK 16
__global__ __launch_bounds__(256) void sgemm_kernel(
    const float* __restrict__ A, int lda,
    const float* __restrict__ Bm, int ldb,
    const float* __restrict__ bias,
    __half* __restrict__ Cm, int ldc, int K)
{
    __shared__ __align__(16) float As[2][BKK][BM + 4];
    __shared__ __align__(16) float Bs[2][BKK][BN];
    const int tid = threadIdx.x;
    const int tx = tid & 15, ty = tid >> 4;
    const int row0 = blockIdx.y * BM, col0 = blockIdx.x * BN;
    const int m0 = ty * 8, n0 = tx * 4;
    const int arow = tid >> 2, akq = (tid & 3) * 4;
    const int bk = tid >> 4, bn = (tid & 15) * 4;

    float acc[8][4];
    #pragma unroll
    for (int i = 0; i < 8; i++)
        #pragma unroll
        for (int j = 0; j < 4; j++) acc[i][j] = 0.0f;
    float4 ra[2], rb;

    auto gload = [&](int kt) {
        const int kbase = kt * BKK;
        #pragma unroll
        for (int i = 0; i < 2; i++) {
            int r = arow + i * 64, k = kbase + akq;
            const float* p = A + (size_t)(row0 + r) * lda + k;
            float4 v;
            v.x = (k + 0 < K) ? p[0] : 0.0f;
            v.y = (k + 1 < K) ? p[1] : 0.0f;
            v.z = (k + 2 < K) ? p[2] : 0.0f;
            v.w = (k + 3 < K) ? p[3] : 0.0f;
            ra[i] = v;
        }
        int k = kbase + bk;
        const float* p = Bm + (size_t)k * ldb + col0 + bn;
        rb = (k < K) ? *reinterpret_cast<const float4*>(p) : make_float4(0, 0, 0, 0);
    };
    auto sstore = [&](int buf) {
        #pragma unroll
        for (int i = 0; i < 2; i++) {
            int r = arow + i * 64;
            As[buf][akq + 0][r] = ra[i].x;
            As[buf][akq + 1][r] = ra[i].y;
            As[buf][akq + 2][r] = ra[i].z;
            As[buf][akq + 3][r] = ra[i].w;
        }
        *reinterpret_cast<float4*>(&Bs[buf][bk][bn]) = rb;
    };

    const int ktiles = (K + BKK - 1) / BKK;
    gload(0); sstore(0); __syncthreads();
    for (int kt = 0; kt < ktiles; kt++) {
        const int buf = kt & 1;
        if (kt + 1 < ktiles) gload(kt + 1);
        #pragma unroll
        for (int kk = 0; kk < BKK; kk++) {
            float a[8], bv[4];
            #pragma unroll
            for (int i = 0; i < 8; i++) a[i] = As[buf][kk][m0 + i];
            #pragma unroll
            for (int j = 0; j < 4; j++) bv[j] = Bs[buf][kk][n0 + j];
            #pragma unroll
            for (int i = 0; i < 8; i++)
                #pragma unroll
                for (int j = 0; j < 4; j++)
                    acc[i][j] = fmaf(a[i], bv[j], acc[i][j]);
        }
        if (kt + 1 < ktiles) sstore(buf ^ 1);
        __syncthreads();
    }
    float bb[4];
    #pragma unroll
    for (int j = 0; j < 4; j++) bb[j] = bias[col0 + n0 + j];
    #pragma unroll
    for (int i = 0; i < 8; i++) {
        const int m = row0 + m0 + i;
        __half2 h01 = __floats2half2_rn(acc[i][0] + bb[0], acc[i][1] + bb[1]);
        __half2 h23 = __floats2half2_rn(acc[i][2] + bb[2], acc[i][3] + bb[3]);
        __half2* dst = reinterpret_cast<__half2*>(Cm + (size_t)m * ldc + col0 + n0);
        dst[0] = h01; dst[1] = h23;
    }
}

// ===================== fp16 HMMA GEMM common ================================
#define GBM 128
#define GBN 64
#define GBK 64
#define GSTAGES 3
#define OFF_A 0
#define OFF_B 16384
#define STAGE_BYTES 24576
#define GSMEM_TOTAL (GSTAGES * STAGE_BYTES)

__device__ __forceinline__ uint32_t soff(int r, int ch) {
    return (uint32_t)(r * 128 + (((ch ^ r) & 7) << 4));
}

// Mainloop shared by both GEMM variants; computes acc[2][4][4].
#define GEMM_MAINLOOP(A_, W_)                                                           \
    auto load_stage = [&](int kt) {                                                     \
        const uint32_t sb = sbase + (uint32_t)(kt % GSTAGES) * STAGE_BYTES;             \
        const int kb = kt * GBK;                                                        \
        _Pragma("unroll")                                                               \
        for (int i = 0; i < 4; i++) {                                                   \
            int c = tid + i * 256;                                                      \
            int r = c >> 3, ch = c & 7;                                                 \
            CP_ASYNC16(sb + OFF_A + soff(r, ch), A_ + (size_t)(row0 + r) * H_ + kb + ch * 8); \
        }                                                                               \
        _Pragma("unroll")                                                               \
        for (int i = 0; i < 2; i++) {                                                   \
            int c = tid + i * 256;                                                      \
            int r = c >> 3, ch = c & 7;                                                 \
            CP_ASYNC16(sb + OFF_B + soff(r, ch), W_ + (size_t)(col0 + r) * H_ + kb + ch * 8); \
        }                                                                               \
    };                                                                                  \
    const int a_r = wm * 32 + (lane & 15);                                              \
    const int a_half = lane >> 4;                                                       \
    const int b_r = wn * 32 + (lane & 7) + ((lane >> 4) << 3);                          \
    const int b_half = (lane >> 3) & 1;                                                 \
    load_stage(0); CP_COMMIT();                                                         \
    load_stage(1); CP_COMMIT();                                                         \
    uint32_t af[2][2][4];                                                               \
    uint32_t bf[2][2][4];                                                               \
    const int NKT = H_ / GBK;                                                           \
    for (int kt = 0; kt < NKT; kt++) {                                                  \
        CP_WAIT1();                                                                     \
        __syncthreads();                                                                \
        const uint32_t sb = sbase + (uint32_t)(kt % GSTAGES) * STAGE_BYTES;             \
        _Pragma("unroll")                                                               \
        for (int mi = 0; mi < 2; mi++)                                                  \
            ldsm4(af[0][mi], sb + OFF_A + soff(a_r + mi * 16, a_half));                 \
        _Pragma("unroll")                                                               \
        for (int nt = 0; nt < 2; nt++)                                                  \
            ldsm4(bf[0][nt], sb + OFF_B + soff(b_r + nt * 16, b_half));                 \
        _Pragma("unroll")                                                               \
        for (int ks = 0; ks < 4; ks++) {                                                \
            const int cur = ks & 1, nxt = cur ^ 1;                                      \
            if (ks < 3) {                                                               \
                const int ch = (ks + 1) * 2;                                            \
                _Pragma("unroll")                                                       \
                for (int mi = 0; mi < 2; mi++)                                          \
                    ldsm4(af[nxt][mi], sb + OFF_A + soff(a_r + mi * 16, ch + a_half));  \
                _Pragma("unroll")                                                       \
                for (int nt = 0; nt < 2; nt++)                                          \
                    ldsm4(bf[nxt][nt], sb + OFF_B + soff(b_r + nt * 16, ch + b_half));  \
            }                                                                           \
            if (ks == 0) {                                                              \
                if (kt + 2 < NKT) load_stage(kt + 2);                                   \
                CP_COMMIT();                                                            \
            }                                                                           \
            _Pragma("unroll")                                                           \
            for (int mi = 0; mi < 2; mi++)                                              \
                _Pragma("unroll")                                                       \
                for (int ni = 0; ni < 4; ni++)                                          \
                    mma16816h(acc[mi][ni], af[cur][mi], &bf[cur][ni >> 1][(ni & 1) * 2]); \
        }                                                                               \
    }

// ---- variant 1: silu + fp16 store (layers 1, 2) ----
__global__ __launch_bounds__(256, 1) void gemm_hmma(
    const __half* __restrict__ A, const __half* __restrict__ W,
    const float* __restrict__ bias, __half* __restrict__ outC)
{
    extern __shared__ __align__(1024) char gs[];
    const uint32_t sbase = smem_to_u32(gs);
    const int tid = threadIdx.x;
    const int row0 = blockIdx.y * GBM;
    const int col0 = blockIdx.x * GBN;
    const int lane = tid & 31;
    const int wid = tid >> 5;
    const int wm = wid & 3;
    const int wn = wid >> 2;

    float acc[2][4][4];
    #pragma unroll
    for (int mi = 0; mi < 2; mi++)
        #pragma unroll
        for (int ni = 0; ni < 4; ni++)
            #pragma unroll
            for (int q = 0; q < 4; q++) acc[mi][ni][q] = 0.0f;

    GEMM_MAINLOOP(A, W)

    #pragma unroll
    for (int mi = 0; mi < 2; mi++) {
        const int r0g = row0 + wm * 32 + mi * 16 + (lane >> 2);
        #pragma unroll
        for (int ni = 0; ni < 4; ni++) {
            const int cg = col0 + wn * 32 + ni * 8 + (lane & 3) * 2;
            float2 bb = *reinterpret_cast<const float2*>(bias + cg);
            __half2 p0 = __floats2half2_rn(silu_f(acc[mi][ni][0] + bb.x),
                                           silu_f(acc[mi][ni][1] + bb.y));
            __half2 p1 = __floats2half2_rn(silu_f(acc[mi][ni][2] + bb.x),
                                           silu_f(acc[mi][ni][3] + bb.y));
            *reinterpret_cast<__half2*>(outC + (size_t)r0g * H_ + cg) = p0;
            *reinterpret_cast<__half2*>(outC + (size_t)(r0g + 8) * H_ + cg) = p1;
        }
    }
}

// ---- variant 2: layer 3 — silu then fold output head, write partials ----
__global__ __launch_bounds__(256, 1) void gemm_hmma_last(
    const __half* __restrict__ A, const __half* __restrict__ W,
    const float* __restrict__ bias, const float* __restrict__ W4,
    float* __restrict__ part)
{
    extern __shared__ __align__(1024) char gs[];
    __shared__ float spart[128 * 2];
    const uint32_t sbase = smem_to_u32(gs);
    const int tid = threadIdx.x;
    const int row0 = blockIdx.y * GBM;
    const int col0 = blockIdx.x * GBN;
    const int lane = tid & 31;
    const int wid = tid >> 5;
    const int wm = wid & 3;
    const int wn = wid >> 2;

    float acc[2][4][4];
    #pragma unroll
    for (int mi = 0; mi < 2; mi++)
        #pragma unroll
        for (int ni = 0; ni < 4; ni++)
            #pragma unroll
            for (int q = 0; q < 4; q++) acc[mi][ni][q] = 0.0f;

    GEMM_MAINLOOP(A, W)

    // epilogue: silu, multiply by W4 columns, reduce to per-row partials
    const float2* w4 = reinterpret_cast<const float2*>(W4);
    float sum[2][2][2];  // [mi][rhalf][c]
    #pragma unroll
    for (int mi = 0; mi < 2; mi++)
        #pragma unroll
        for (int rh = 0; rh < 2; rh++) { sum[mi][rh][0] = 0.0f; sum[mi][rh][1] = 0.0f; }

    #pragma unroll
    for (int mi = 0; mi < 2; mi++) {
        #pragma unroll
        for (int ni = 0; ni < 4; ni++) {
            const int cg = col0 + wn * 32 + ni * 8 + (lane & 3) * 2;
            float2 bb = *reinterpret_cast<const float2*>(bias + cg);
            float2 w0 = w4[cg], w1 = w4[cg + 1];
            float h00 = silu_f(acc[mi][ni][0] + bb.x);
            float h01 = silu_f(acc[mi][ni][1] + bb.y);
            float h10 = silu_f(acc[mi][ni][2] + bb.x);
            float h11 = silu_f(acc[mi][ni][3] + bb.y);
            sum[mi][0][0] += h00 * w0.x + h01 * w1.x;
            sum[mi][0][1] += h00 * w0.y + h01 * w1.y;
            sum[mi][1][0] += h10 * w0.x + h11 * w1.x;
            sum[mi][1][1] += h10 * w0.y + h11 * w1.y;
        }
    }
    // quad reduction (lane&3)
    #pragma unroll
    for (int mi = 0; mi < 2; mi++)
        #pragma unroll
        for (int rh = 0; rh < 2; rh++)
            #pragma unroll
            for (int c = 0; c < 2; c++) {
                float v = sum[mi][rh][c];
                v += __shfl_xor_sync(0xffffffffu, v, 1);
                v += __shfl_xor_sync(0xffffffffu, v, 2);
                sum[mi][rh][c] = v;
            }
    // combine the two N-warps via smem
    if (wn == 0 && (lane & 3) == 0) {
        #pragma unroll
        for (int mi = 0; mi < 2; mi++)
            #pragma unroll
            for (int rh = 0; rh < 2; rh++) {
                int r = wm * 32 + mi * 16 + rh * 8 + (lane >> 2);
                spart[r * 2 + 0] = sum[mi][rh][0];
                spart[r * 2 + 1] = sum[mi][rh][1];
            }
    }
    __syncthreads();
    if (wn == 1 && (lane & 3) == 0) {
        #pragma unroll
        for (int mi = 0; mi < 2; mi++)
            #pragma unroll
            for (int rh = 0; rh < 2; rh++) {
                int r = wm * 32 + mi * 16 + rh * 8 + (lane >> 2);
                spart[r * 2 + 0] += sum[mi][rh][0];
                spart[r * 2 + 1] += sum[mi][rh][1];
            }
    }
    __syncthreads();
    // write this CTA's 128x2 partial slice
    float* dst = part + ((size_t)(blockIdx.y * 16 + blockIdx.x) * 256);
    if (tid < 256) dst[tid] = spart[tid];
}

// ===================== layer-0 fused activation (step 0 only) ===============
__global__ __launch_bounds__(256) void layer0_act(
    const __half* __restrict__ base0h, const float* __restrict__ tvec_step,
    const float* __restrict__ w254, const float* __restrict__ w255,
    const float* __restrict__ x, __half* __restrict__ h)
{
    const int idx = blockIdx.x * blockDim.x + threadIdx.x;
    const int b = idx >> 10;
    const int j = idx & 1023;
    float v = __half2float(base0h[idx]) + tvec_step[j]
              + x[2 * b] * w254[j] + x[2 * b + 1] * w255[j];
    h[idx] = __float2half_rn(silu_f(v));
}

// ===================== fused: partial-sum + Euler + next-step layer0 ========
// 128 blocks x 256 threads; block handles 8 rows (warp-per-row).
__global__ __launch_bounds__(256) void step_fuse(
    const float* __restrict__ part,
    const float* __restrict__ b4,
    float* __restrict__ x,
    const __half* __restrict__ base0h, const float* __restrict__ tvec_next,
    const float* __restrict__ w254, const float* __restrict__ w255,
    __half* __restrict__ hOut)
{
    const int tid = threadIdx.x;
    const int lane = tid & 31;
    const int wid = tid >> 5;
    const int rbase = blockIdx.x * 8;

    __shared__ float sx[8][2];

    {
        const int row = rbase + wid;
        const int by = row >> 7, rl = row & 127;
        float v0 = 0.0f, v1 = 0.0f;
        if (lane < 16) {
            const float* p = part + ((size_t)(by * 16 + lane) * 128 + rl) * 2;
            v0 = p[0]; v1 = p[1];
        }
        #pragma unroll
        for (int o = 8; o > 0; o >>= 1) {
            v0 += __shfl_down_sync(0xffffffffu, v0, o);
            v1 += __shfl_down_sync(0xffffffffu, v1, o);
        }
        if (lane == 0) {
            float xv0 = x[2 * row]     + DT * (v0 + b4[0]);
            float xv1 = x[2 * row + 1] + DT * (v1 + b4[1]);
            x[2 * row] = xv0; x[2 * row + 1] = xv1;
            sx[wid][0] = xv0; sx[wid][1] = xv1;
        }
    }
    __syncthreads();

    for (int idx = tid; idx < 8 * H_; idx += 256) {
        const int r = idx >> 10;
        const int j = idx & 1023;
        const int b = rbase + r;
        float v = __half2float(base0h[(size_t)b * H_ + j]) + tvec_next[j]
                  + sx[r][0] * w254[j] + sx[r][1] * w255[j];
        hOut[(size_t)b * H_ + j] = __float2half_rn(silu_f(v));
    }
}

// ===================== final: partial-sum + Euler -> out ====================
__global__ __launch_bounds__(256) void out_euler(
    const float* __restrict__ part,
    const float* __restrict__ b4,
    const float* __restrict__ x, float* __restrict__ out)
{
    const int tid = threadIdx.x;
    const int lane = tid & 31;
    const int wid = tid >> 5;
    const int row = blockIdx.x * 8 + wid;
    const int by = row >> 7, rl = row & 127;
    float v0 = 0.0f, v1 = 0.0f;
    if (lane < 16) {
        const float* p = part + ((size_t)(by * 16 + lane) * 128 + rl) * 2;
        v0 = p[0]; v1 = p[1];
    }
    #pragma unroll
    for (int o = 8; o > 0; o >>= 1) {
        v0 += __shfl_down_sync(0xffffffffu, v0, o);
        v1 += __shfl_down_sync(0xffffffffu, v1, o);
    }
    if (lane == 0) {
        out[2 * row]     = x[2 * row]     + DT * (v0 + b4[0]);
        out[2 * row + 1] = x[2 * row + 1] + DT * (v1 + b4[1]);
    }
}

// ===================== host side ============================================
extern "C" void kernel_launch(void* const* d_in, const int* in_sizes, int n_in,
                              void* d_out, int out_size)
{
    const float* state = (const float*)d_in[0];
    const float* x0    = (const float*)d_in[1];
    const float* W0    = (const float*)d_in[2];
    const float* b0    = (const float*)d_in[3];
    const float* W1    = (const float*)d_in[4];
    const float* b1    = (const float*)d_in[5];
    const float* W2    = (const float*)d_in[6];
    const float* b2    = (const float*)d_in[7];
    const float* W3    = (const float*)d_in[8];
    const float* b3    = (const float*)d_in[9];
    const float* W4    = (const float*)d_in[10];
    const float* b4    = (const float*)d_in[11];
    float* out = (float*)d_out;

    float *tvecp, *xp, *partp;
    __half *base0h, *actA, *actB, *w16;
    cudaGetSymbolAddress((void**)&base0h, g_base0h);
    cudaGetSymbolAddress((void**)&tvecp,  g_tvec);
    cudaGetSymbolAddress((void**)&xp,     g_x);
    cudaGetSymbolAddress((void**)&actA,   g_actA);
    cudaGetSymbolAddress((void**)&actB,   g_actB);
    cudaGetSymbolAddress((void**)&w16,    g_w16);
    cudaGetSymbolAddress((void**)&partp,  g_part);

    static bool attr_set = false;
    if (!attr_set) {
        cudaFuncSetAttribute(gemm_hmma, cudaFuncAttributeMaxDynamicSharedMemorySize,
                             GSMEM_TOTAL);
        cudaFuncSetAttribute(gemm_hmma_last, cudaFuncAttributeMaxDynamicSharedMemorySize,
                             GSMEM_TOTAL);
        attr_set = true;
    }

    // one-time prep
    cudaMemcpyAsync(xp, x0, B_ * C_ * sizeof(float), cudaMemcpyDeviceToDevice);
    dim3 tb(32, 8), tg(32, 32);
    wconv_kernel<<<tg, tb>>>(W1, w16 + 0 * (size_t)H_ * H_);
    wconv_kernel<<<tg, tb>>>(W2, w16 + 1 * (size_t)H_ * H_);
    wconv_kernel<<<tg, tb>>>(W3, w16 + 2 * (size_t)H_ * H_);
    tvec_kernel<<<dim3(NSTEPS, 8), 128>>>(W0, tvecp);
    sgemm_kernel<<<dim3(H_ / BN, B_ / BM), 256>>>(state, S_, W0, H_, b0, base0h, H_, S_);

    const float* w254 = W0 + (size_t)254 * H_;
    const float* w255 = W0 + (size_t)255 * H_;

    dim3 ggrid(H_ / GBN, B_ / GBM);  // (16, 8) = 128 CTAs
    layer0_act<<<(B_ * H_) / 256, 256>>>(base0h, tvecp, w254, w255, xp, actA);
    for (int i = 0; i < NSTEPS; i++) {
        gemm_hmma<<<ggrid, 256, GSMEM_TOTAL>>>(actA, w16 + 0 * (size_t)H_ * H_, b1, actB);
        gemm_hmma<<<ggrid, 256, GSMEM_TOTAL>>>(actB, w16 + 1 * (size_t)H_ * H_, b2, actA);
        gemm_hmma_last<<<ggrid, 256, GSMEM_TOTAL>>>(actA, w16 + 2 * (size_t)H_ * H_,
                                                    b3, W4, partp);
        if (i + 1 < NSTEPS) {
            step_fuse<<<B_ / 8, 256>>>(partp, b4, xp, base0h,
                                       tvecp + (i + 1) * H_, w254, w255, actA);
        } else {
            out_euler<<<B_ / 8, 256>>>(partp, b4, xp, out);
        }
    }
}